// round 3
// baseline (speedup 1.0000x reference)
#include <cuda_runtime.h>

#define N_MAT   100000
#define N_ELEM  118
#define HID     128
#define NHEADS  8
#define F_MAT   128
#define F_ELEM  64
#define OUT_DIM 64
#define E_EM    1000000
#define E_MM    2000000
#define NEG_SLOPE 0.2f

// ---------------- scratch (static device globals; no allocation) ----------------
__device__ float g_h_mat[(size_t)N_MAT * HID];    // 51.2 MB
__device__ float g_h_elem[N_ELEM * HID];
__device__ float g_as_em[N_ELEM * NHEADS];
__device__ float g_ad_em[N_MAT * NHEADS];
__device__ float g_as_mm[N_MAT * NHEADS];
__device__ float g_ad_mm[N_MAT * NHEADS];
__device__ float g_o_em[(size_t)N_MAT * HID];     // 51.2 MB
__device__ float g_o_mm[(size_t)N_MAT * HID];     // 51.2 MB
__device__ float g_red[2 * HID];
__device__ float g_attn[2];

// CSR scratch
__device__ int g_cnt_em[N_MAT];
__device__ int g_off_em[N_MAT];
__device__ int g_cur_em[N_MAT];
__device__ int g_srt_em[E_EM];
__device__ int g_cnt_mm[N_MAT];
__device__ int g_off_mm[N_MAT];
__device__ int g_cur_mm[N_MAT];
__device__ int g_srt_mm[E_MM];

// ---------------- zero counters + reduction buffer ----------------
__global__ void zero_kernel() {
    int i = blockIdx.x * blockDim.x + threadIdx.x;
    int nt = gridDim.x * blockDim.x;
    for (int k = i; k < N_MAT; k += nt) { g_cnt_em[k] = 0; g_cnt_mm[k] = 0; }
    if (i < 2 * HID) g_red[i] = 0.f;
}

// ---------------- degree histogram ----------------
__global__ void hist_kernel(const int* __restrict__ dst, int E, int type) {
    int* cnt = type ? g_cnt_mm : g_cnt_em;
    int e = blockIdx.x * blockDim.x + threadIdx.x;
    if (e < E) atomicAdd(&cnt[dst[e]], 1);
}

// ---------------- single-block exclusive scan over N_MAT counts ----------------
__global__ void scan_kernel(int type) {
    const int* cnt = type ? g_cnt_mm : g_cnt_em;
    int* off = type ? g_off_mm : g_off_em;
    int* cur = type ? g_cur_mm : g_cur_em;
    const int T = 1024;
    int t = threadIdx.x;
    int chunk = (N_MAT + T - 1) / T;
    int lo = t * chunk;
    int hi = lo + chunk; if (hi > N_MAT) hi = N_MAT; if (lo > N_MAT) lo = N_MAT;
    int s = 0;
    for (int i = lo; i < hi; i++) s += cnt[i];
    __shared__ int wsum[32];
    int lane = t & 31, wid = t >> 5;
    int v = s;
#pragma unroll
    for (int o = 1; o < 32; o <<= 1) {
        int u = __shfl_up_sync(0xffffffffu, v, o);
        if (lane >= o) v += u;
    }
    if (lane == 31) wsum[wid] = v;
    __syncthreads();
    if (wid == 0) {
        int w = wsum[lane];
#pragma unroll
        for (int o = 1; o < 32; o <<= 1) {
            int u = __shfl_up_sync(0xffffffffu, w, o);
            if (lane >= o) w += u;
        }
        wsum[lane] = w;
    }
    __syncthreads();
    int run = (v - s) + (wid > 0 ? wsum[wid - 1] : 0);
    for (int i = lo; i < hi; i++) {
        off[i] = run; cur[i] = run;
        run += cnt[i];
    }
}

// ---------------- scatter src ids into CSR order ----------------
__global__ void scatter_kernel(const int* __restrict__ src, const int* __restrict__ dst,
                               int E, int type) {
    int* cur = type ? g_cur_mm : g_cur_em;
    int* srt = type ? g_srt_mm : g_srt_em;
    int e = blockIdx.x * blockDim.x + threadIdx.x;
    if (e >= E) return;
    int d = dst[e];
    int p = atomicAdd(&cur[d], 1);
    srt[p] = src[e];
}

// ---------------- projection: mat nodes (F=128), 8 nodes/block ----------------
__global__ void proj_mat_kernel(const float* __restrict__ x, const float* __restrict__ W,
                                const float* __restrict__ b,
                                const float* __restrict__ a_ad_em,
                                const float* __restrict__ a_as_mm,
                                const float* __restrict__ a_ad_mm) {
    __shared__ float xs[8][F_MAT];
    int t = threadIdx.x;              // 0..127 -> output channel
    int n0 = blockIdx.x * 8;
    const float4* xg = (const float4*)(x + (size_t)n0 * F_MAT);
    float4* xs4 = (float4*)&xs[0][0];
    xs4[t] = xg[t];
    xs4[t + 128] = xg[t + 128];
    __syncthreads();

    float acc[8];
#pragma unroll
    for (int i = 0; i < 8; i++) acc[i] = 0.f;
    const float4* Wr = (const float4*)(W + (size_t)t * F_MAT);
#pragma unroll 8
    for (int k4 = 0; k4 < F_MAT / 4; k4++) {
        float4 wv = Wr[k4];
#pragma unroll
        for (int i = 0; i < 8; i++) {
            float4 xv = *(const float4*)&xs[i][k4 * 4];
            acc[i] += wv.x * xv.x + wv.y * xv.y + wv.z * xv.z + wv.w * xv.w;
        }
    }
    float bb = b[t];
    float ae = a_ad_em[t], am1 = a_as_mm[t], am2 = a_ad_mm[t];
    int head = t >> 4;
#pragma unroll
    for (int i = 0; i < 8; i++) {
        float h = acc[i] + bb;
        g_h_mat[(size_t)(n0 + i) * HID + t] = h;
        float v1 = h * ae, v2 = h * am1, v3 = h * am2;
#pragma unroll
        for (int off = 8; off; off >>= 1) {
            v1 += __shfl_down_sync(0xffffffffu, v1, off);
            v2 += __shfl_down_sync(0xffffffffu, v2, off);
            v3 += __shfl_down_sync(0xffffffffu, v3, off);
        }
        if ((t & 15) == 0) {
            g_ad_em[(n0 + i) * NHEADS + head] = v1;
            g_as_mm[(n0 + i) * NHEADS + head] = v2;
            g_ad_mm[(n0 + i) * NHEADS + head] = v3;
        }
    }
}

// ---------------- projection: elem nodes (F=64), 1 node/block ----------------
__global__ void proj_elem_kernel(const float* __restrict__ x, const float* __restrict__ W,
                                 const float* __restrict__ b, const float* __restrict__ a_src) {
    __shared__ float xs[F_ELEM];
    int t = threadIdx.x;   // 0..127
    int n = blockIdx.x;
    if (t < F_ELEM) xs[t] = x[n * F_ELEM + t];
    __syncthreads();
    float acc = b[t];
    const float4* Wr = (const float4*)(W + (size_t)t * F_ELEM);
#pragma unroll
    for (int k4 = 0; k4 < F_ELEM / 4; k4++) {
        float4 wv = Wr[k4];
        float4 xv = *(const float4*)&xs[k4 * 4];
        acc += wv.x * xv.x + wv.y * xv.y + wv.z * xv.z + wv.w * xv.w;
    }
    g_h_elem[n * HID + t] = acc;
    float v = acc * a_src[t];
#pragma unroll
    for (int off = 8; off; off >>= 1) v += __shfl_down_sync(0xffffffffu, v, off);
    if ((t & 15) == 0) g_as_em[n * NHEADS + (t >> 4)] = v;
}

// ---------------- CSR aggregation: warp per dst, fused den+numerator ----------------
// out[d] = (sum_e ex_e * h[src_e]) / (sum_e ex_e + 1e-16)  -- identical to softmax ratio
__global__ void agg_csr_kernel(int type) {
    const int* srt  = type ? g_srt_mm : g_srt_em;
    const int* off  = type ? g_off_mm : g_off_em;
    const int* cnt  = type ? g_cnt_mm : g_cnt_em;
    const float* as = type ? g_as_mm : g_as_em;
    const float* ad = type ? g_ad_mm : g_ad_em;
    const float* h  = type ? g_h_mat : g_h_elem;
    float* o        = type ? g_o_mm : g_o_em;

    int warp = (blockIdx.x * blockDim.x + threadIdx.x) >> 5;
    if (warp >= N_MAT) return;
    int lane = threadIdx.x & 31;
    int d = warp;
    int start = __ldg(&off[d]), deg = __ldg(&cnt[d]);
    float adv = __ldg(&ad[(size_t)d * NHEADS + (lane & 7)]);
    float4 acc = make_float4(0.f, 0.f, 0.f, 0.f);
    float den = 0.f;
    for (int j = 0; j < deg; j += 32) {
        int myi = j + lane;
        int s_my = (myi < deg) ? __ldg(&srt[start + myi]) : 0;
        int m = deg - j; if (m > 32) m = 32;
        for (int k = 0; k < m; k++) {
            int s = __shfl_sync(0xffffffffu, s_my, k);
            float asv = __ldg(&as[(size_t)s * NHEADS + (lane & 7)]);
            float a = asv + adv;
            a = a > 0.f ? a : NEG_SLOPE * a;
            float ex = __expf(a);
            den += ex;
            float w = __shfl_sync(0xffffffffu, ex, lane >> 2);   // head = lane/4
            float4 v = __ldg((const float4*)(h + (size_t)s * HID) + lane);
            acc.x += w * v.x; acc.y += w * v.y; acc.z += w * v.z; acc.w += w * v.w;
        }
    }
    float dh = __shfl_sync(0xffffffffu, den, lane >> 2);
    float inv = 1.f / (dh + 1e-16f);
    acc.x *= inv; acc.y *= inv; acc.z *= inv; acc.w *= inv;
    ((float4*)(o + (size_t)d * HID))[lane] = acc;
}

// ---------------- semantic score: sum_n tanh(relu(o) @ Wk^T + bk), per m ----------------
__global__ void score_kernel(const float* __restrict__ Wk, const float* __restrict__ bk, int m) {
    __shared__ float ss[8][HID];
    int t = threadIdx.x;         // channel c
    int n0 = blockIdx.x * 8;
    const float* o = m ? g_o_mm : g_o_em;
    const float4* og = (const float4*)(o + (size_t)n0 * HID);
    float4* ss4 = (float4*)&ss[0][0];
    float4 v = og[t];
    v.x = fmaxf(v.x, 0.f); v.y = fmaxf(v.y, 0.f); v.z = fmaxf(v.z, 0.f); v.w = fmaxf(v.w, 0.f);
    ss4[t] = v;
    v = og[t + 128];
    v.x = fmaxf(v.x, 0.f); v.y = fmaxf(v.y, 0.f); v.z = fmaxf(v.z, 0.f); v.w = fmaxf(v.w, 0.f);
    ss4[t + 128] = v;
    __syncthreads();

    float acc[8];
#pragma unroll
    for (int i = 0; i < 8; i++) acc[i] = 0.f;
    const float4* Wr = (const float4*)(Wk + (size_t)t * HID);
#pragma unroll 8
    for (int k4 = 0; k4 < HID / 4; k4++) {
        float4 wv = Wr[k4];
#pragma unroll
        for (int i = 0; i < 8; i++) {
            float4 xv = *(const float4*)&ss[i][k4 * 4];
            acc[i] += wv.x * xv.x + wv.y * xv.y + wv.z * xv.z + wv.w * xv.w;
        }
    }
    float bb = bk[t];
    float local = 0.f;
#pragma unroll
    for (int i = 0; i < 8; i++) local += tanhf(acc[i] + bb);
    atomicAdd(&g_red[m * HID + t], local);
}

// ---------------- semantic attention weights (softmax over 2 scores) ----------------
__global__ void attn_kernel(const float* __restrict__ q) {
    int t = threadIdx.x;   // 128 threads
    float qv = q[t];
    float s0 = qv * g_red[t];
    float s1 = qv * g_red[HID + t];
    __shared__ float r0[4], r1[4];
#pragma unroll
    for (int off = 16; off; off >>= 1) {
        s0 += __shfl_down_sync(0xffffffffu, s0, off);
        s1 += __shfl_down_sync(0xffffffffu, s1, off);
    }
    if ((t & 31) == 0) { r0[t >> 5] = s0; r1[t >> 5] = s1; }
    __syncthreads();
    if (t == 0) {
        float a = (r0[0] + r0[1] + r0[2] + r0[3]) * (1.f / N_MAT);
        float b = (r1[0] + r1[1] + r1[2] + r1[3]) * (1.f / N_MAT);
        float mx = fmaxf(a, b);
        float e0 = __expf(a - mx), e1 = __expf(b - mx);
        float inv = 1.f / (e0 + e1);
        g_attn[0] = e0 * inv;
        g_attn[1] = e1 * inv;
    }
}

// ---------------- final: (attn0*relu(o_em) + attn1*relu(o_mm)) @ Wl^T + bl ----------------
__global__ void final_kernel(const float* __restrict__ Wl, const float* __restrict__ bl,
                             float* __restrict__ out) {
    __shared__ float cs[8][HID];
    int t = threadIdx.x;   // 0..63 -> output channel j
    int n0 = blockIdx.x * 8;
    float a0 = g_attn[0], a1 = g_attn[1];
    const float4* eg = (const float4*)(g_o_em + (size_t)n0 * HID);
    const float4* mg = (const float4*)(g_o_mm + (size_t)n0 * HID);
    float4* cs4 = (float4*)&cs[0][0];
#pragma unroll
    for (int r = 0; r < 4; r++) {
        int idx = r * 64 + t;
        float4 e = eg[idx], mm = mg[idx];
        float4 c;
        c.x = a0 * fmaxf(e.x, 0.f) + a1 * fmaxf(mm.x, 0.f);
        c.y = a0 * fmaxf(e.y, 0.f) + a1 * fmaxf(mm.y, 0.f);
        c.z = a0 * fmaxf(e.z, 0.f) + a1 * fmaxf(mm.z, 0.f);
        c.w = a0 * fmaxf(e.w, 0.f) + a1 * fmaxf(mm.w, 0.f);
        cs4[idx] = c;
    }
    __syncthreads();
    float acc[8];
#pragma unroll
    for (int i = 0; i < 8; i++) acc[i] = 0.f;
    const float4* Wr = (const float4*)(Wl + (size_t)t * HID);
#pragma unroll 8
    for (int k4 = 0; k4 < HID / 4; k4++) {
        float4 wv = Wr[k4];
#pragma unroll
        for (int i = 0; i < 8; i++) {
            float4 xv = *(const float4*)&cs[i][k4 * 4];
            acc[i] += wv.x * xv.x + wv.y * xv.y + wv.z * xv.z + wv.w * xv.w;
        }
    }
    float bb = bl[t];
#pragma unroll
    for (int i = 0; i < 8; i++)
        out[(size_t)(n0 + i) * OUT_DIM + t] = acc[i] + bb;
}

// ---------------- launcher ----------------
extern "C" void kernel_launch(void* const* d_in, const int* in_sizes, int n_in,
                              void* d_out, int out_size) {
    const float* x_mat    = (const float*)d_in[0];
    const float* x_elem   = (const float*)d_in[1];
    const float* W_pm     = (const float*)d_in[2];
    const float* b_pm     = (const float*)d_in[3];
    const float* W_pe     = (const float*)d_in[4];
    const float* b_pe     = (const float*)d_in[5];
    const float* a_src_em = (const float*)d_in[6];
    const float* a_dst_em = (const float*)d_in[7];
    const float* a_src_mm = (const float*)d_in[8];
    const float* a_dst_mm = (const float*)d_in[9];
    const float* Wk       = (const float*)d_in[10];
    const float* bk       = (const float*)d_in[11];
    const float* q        = (const float*)d_in[12];
    const float* Wl       = (const float*)d_in[13];
    const float* bl       = (const float*)d_in[14];
    const int* src_em     = (const int*)d_in[15];
    const int* dst_em     = (const int*)d_in[16];
    const int* src_mm     = (const int*)d_in[17];
    const int* dst_mm     = (const int*)d_in[18];
    float* out = (float*)d_out;

    zero_kernel<<<512, 256>>>();

    // CSR build for both edge types (scratch selected inside kernels by type flag)
    hist_kernel<<<(E_EM + 255) / 256, 256>>>(dst_em, E_EM, 0);
    hist_kernel<<<(E_MM + 255) / 256, 256>>>(dst_mm, E_MM, 1);
    scan_kernel<<<1, 1024>>>(0);
    scan_kernel<<<1, 1024>>>(1);
    scatter_kernel<<<(E_EM + 255) / 256, 256>>>(src_em, dst_em, E_EM, 0);
    scatter_kernel<<<(E_MM + 255) / 256, 256>>>(src_mm, dst_mm, E_MM, 1);

    // projections
    proj_elem_kernel<<<N_ELEM, 128>>>(x_elem, W_pe, b_pe, a_src_em);
    proj_mat_kernel<<<N_MAT / 8, 128>>>(x_mat, W_pm, b_pm, a_dst_em, a_src_mm, a_dst_mm);

    // fused gather aggregation (no float atomics)
    agg_csr_kernel<<<(N_MAT * 32 + 255) / 256, 256>>>(0);
    agg_csr_kernel<<<(N_MAT * 32 + 255) / 256, 256>>>(1);

    // semantic attention + final linear
    score_kernel<<<N_MAT / 8, 128>>>(Wk, bk, 0);
    score_kernel<<<N_MAT / 8, 128>>>(Wk, bk, 1);
    attn_kernel<<<1, 128>>>(q);
    final_kernel<<<N_MAT / 8, 64>>>(Wl, bl, out);
}

// round 4
// speedup vs baseline: 1.2459x; 1.2459x over previous
#include <cuda_runtime.h>

#define N_MAT   100000
#define N_ELEM  118
#define HID     128
#define NHEADS  8
#define F_MAT   128
#define F_ELEM  64
#define OUT_DIM 64
#define E_EM    1000000
#define E_MM    2000000
#define NEG_SLOPE 0.2f
#define SCAN_BLOCKS 98          // ceil(100000/1024)

// ---------------- scratch (static device globals; no allocation) ----------------
__device__ float g_h_mat[(size_t)N_MAT * HID];    // 51.2 MB
__device__ float g_h_elem[N_ELEM * HID];
__device__ float g_as_em[N_ELEM * NHEADS];
__device__ float g_ad_em[N_MAT * NHEADS];
__device__ float g_as_mm[N_MAT * NHEADS];
__device__ float g_ad_mm[N_MAT * NHEADS];
__device__ float g_o_em[(size_t)N_MAT * HID];     // 51.2 MB
__device__ float g_o_mm[(size_t)N_MAT * HID];     // 51.2 MB
__device__ float g_red[2 * HID];
__device__ float g_attn[2];

// CSR scratch
__device__ int g_cnt_em[N_MAT];
__device__ int g_off_em[N_MAT];
__device__ int g_cur_em[N_MAT];
__device__ int g_srt_em[E_EM];
__device__ int g_cnt_mm[N_MAT];
__device__ int g_off_mm[N_MAT];
__device__ int g_cur_mm[N_MAT];
__device__ int g_srt_mm[E_MM];
__device__ int g_bsum[2 * SCAN_BLOCKS];

// ---------------- zero counters + reduction buffer ----------------
__global__ void zero_kernel() {
    int i = blockIdx.x * blockDim.x + threadIdx.x;
    int nt = gridDim.x * blockDim.x;
    for (int k = i; k < N_MAT; k += nt) { g_cnt_em[k] = 0; g_cnt_mm[k] = 0; }
    if (i < 2 * HID) g_red[i] = 0.f;
}

// ---------------- degree histogram ----------------
__global__ void hist_kernel(const int* __restrict__ dst, int E, int type) {
    int* cnt = type ? g_cnt_mm : g_cnt_em;
    int e = blockIdx.x * blockDim.x + threadIdx.x;
    if (e < E) atomicAdd(&cnt[dst[e]], 1);
}

// ---------------- scan stage 1: per-block sums (grid (98,2)) ----------------
__global__ void scan1_kernel() {
    int type = blockIdx.y;
    const int* cnt = type ? g_cnt_mm : g_cnt_em;
    int i = blockIdx.x * 1024 + threadIdx.x;
    int v = (i < N_MAT) ? cnt[i] : 0;
    int lane = threadIdx.x & 31, wid = threadIdx.x >> 5;
#pragma unroll
    for (int o = 16; o; o >>= 1) v += __shfl_down_sync(0xffffffffu, v, o);
    __shared__ int ws[32];
    if (lane == 0) ws[wid] = v;
    __syncthreads();
    if (wid == 0) {
        int w = ws[lane];
#pragma unroll
        for (int o = 16; o; o >>= 1) w += __shfl_down_sync(0xffffffffu, w, o);
        if (lane == 0) g_bsum[type * SCAN_BLOCKS + blockIdx.x] = w;
    }
}

// ---------------- scan stage 2: exclusive scan of 2x98 block sums ----------------
__global__ void scan2_kernel() {
    __shared__ int sh[2 * SCAN_BLOCKS];
    int t = threadIdx.x;
    if (t < 2 * SCAN_BLOCKS) sh[t] = g_bsum[t];
    __syncthreads();
    if (t < 2) {   // thread t serially scans its type's 98 sums (in shared)
        int run = 0;
        for (int b = 0; b < SCAN_BLOCKS; b++) {
            int v = sh[t * SCAN_BLOCKS + b];
            sh[t * SCAN_BLOCKS + b] = run;
            run += v;
        }
    }
    __syncthreads();
    if (t < 2 * SCAN_BLOCKS) g_bsum[t] = sh[t];
}

// ---------------- scan stage 3: per-block exclusive scan + offset (grid (98,2)) ----------------
__global__ void scan3_kernel() {
    int type = blockIdx.y;
    const int* cnt = type ? g_cnt_mm : g_cnt_em;
    int* off = type ? g_off_mm : g_off_em;
    int* cur = type ? g_cur_mm : g_cur_em;
    int i = blockIdx.x * 1024 + threadIdx.x;
    int v = (i < N_MAT) ? cnt[i] : 0;
    int lane = threadIdx.x & 31, wid = threadIdx.x >> 5;
    int incl = v;
#pragma unroll
    for (int o = 1; o < 32; o <<= 1) {
        int u = __shfl_up_sync(0xffffffffu, incl, o);
        if (lane >= o) incl += u;
    }
    __shared__ int ws[32];
    if (lane == 31) ws[wid] = incl;
    __syncthreads();
    if (wid == 0) {
        int w = ws[lane];
#pragma unroll
        for (int o = 1; o < 32; o <<= 1) {
            int u = __shfl_up_sync(0xffffffffu, w, o);
            if (lane >= o) w += u;
        }
        ws[lane] = w;
    }
    __syncthreads();
    int excl = incl - v + (wid ? ws[wid - 1] : 0) + g_bsum[type * SCAN_BLOCKS + blockIdx.x];
    if (i < N_MAT) { off[i] = excl; cur[i] = excl; }
}

// ---------------- scatter src ids into CSR order ----------------
__global__ void scatter_kernel(const int* __restrict__ src, const int* __restrict__ dst,
                               int E, int type) {
    int* cur = type ? g_cur_mm : g_cur_em;
    int* srt = type ? g_srt_mm : g_srt_em;
    int e = blockIdx.x * blockDim.x + threadIdx.x;
    if (e >= E) return;
    int d = dst[e];
    int p = atomicAdd(&cur[d], 1);
    srt[p] = src[e];
}

// ---------------- projection: mat nodes (F=128), 8 nodes/block ----------------
__global__ void proj_mat_kernel(const float* __restrict__ x, const float* __restrict__ W,
                                const float* __restrict__ b,
                                const float* __restrict__ a_ad_em,
                                const float* __restrict__ a_as_mm,
                                const float* __restrict__ a_ad_mm) {
    __shared__ float xs[8][F_MAT];
    int t = threadIdx.x;              // 0..127 -> output channel
    int n0 = blockIdx.x * 8;
    const float4* xg = (const float4*)(x + (size_t)n0 * F_MAT);
    float4* xs4 = (float4*)&xs[0][0];
    xs4[t] = xg[t];
    xs4[t + 128] = xg[t + 128];
    __syncthreads();

    float acc[8];
#pragma unroll
    for (int i = 0; i < 8; i++) acc[i] = 0.f;
    const float4* Wr = (const float4*)(W + (size_t)t * F_MAT);
#pragma unroll 8
    for (int k4 = 0; k4 < F_MAT / 4; k4++) {
        float4 wv = Wr[k4];
#pragma unroll
        for (int i = 0; i < 8; i++) {
            float4 xv = *(const float4*)&xs[i][k4 * 4];
            acc[i] += wv.x * xv.x + wv.y * xv.y + wv.z * xv.z + wv.w * xv.w;
        }
    }
    float bb = b[t];
    float ae = a_ad_em[t], am1 = a_as_mm[t], am2 = a_ad_mm[t];
    int head = t >> 4;
#pragma unroll
    for (int i = 0; i < 8; i++) {
        float h = acc[i] + bb;
        g_h_mat[(size_t)(n0 + i) * HID + t] = h;
        float v1 = h * ae, v2 = h * am1, v3 = h * am2;
#pragma unroll
        for (int off = 8; off; off >>= 1) {
            v1 += __shfl_down_sync(0xffffffffu, v1, off);
            v2 += __shfl_down_sync(0xffffffffu, v2, off);
            v3 += __shfl_down_sync(0xffffffffu, v3, off);
        }
        if ((t & 15) == 0) {
            g_ad_em[(n0 + i) * NHEADS + head] = v1;
            g_as_mm[(n0 + i) * NHEADS + head] = v2;
            g_ad_mm[(n0 + i) * NHEADS + head] = v3;
        }
    }
}

// ---------------- projection: elem nodes (F=64), 1 node/block ----------------
__global__ void proj_elem_kernel(const float* __restrict__ x, const float* __restrict__ W,
                                 const float* __restrict__ b, const float* __restrict__ a_src) {
    __shared__ float xs[F_ELEM];
    int t = threadIdx.x;   // 0..127
    int n = blockIdx.x;
    if (t < F_ELEM) xs[t] = x[n * F_ELEM + t];
    __syncthreads();
    float acc = b[t];
    const float4* Wr = (const float4*)(W + (size_t)t * F_ELEM);
#pragma unroll
    for (int k4 = 0; k4 < F_ELEM / 4; k4++) {
        float4 wv = Wr[k4];
        float4 xv = *(const float4*)&xs[k4 * 4];
        acc += wv.x * xv.x + wv.y * xv.y + wv.z * xv.z + wv.w * xv.w;
    }
    g_h_elem[n * HID + t] = acc;
    float v = acc * a_src[t];
#pragma unroll
    for (int off = 8; off; off >>= 1) v += __shfl_down_sync(0xffffffffu, v, off);
    if ((t & 15) == 0) g_as_em[n * NHEADS + (t >> 4)] = v;
}

// ---------------- CSR aggregation: warp per dst, fused den+numerator (grid (.,2)) --------
// out[d] = (sum_e ex_e * h[src_e]) / (sum_e ex_e + 1e-16)  -- identical to softmax ratio
__global__ void agg_csr_kernel() {
    int type = blockIdx.y;
    const int* srt  = type ? g_srt_mm : g_srt_em;
    const int* off  = type ? g_off_mm : g_off_em;
    const int* cnt  = type ? g_cnt_mm : g_cnt_em;
    const float* as = type ? g_as_mm : g_as_em;
    const float* ad = type ? g_ad_mm : g_ad_em;
    const float* h  = type ? g_h_mat : g_h_elem;
    float* o        = type ? g_o_mm : g_o_em;

    int warp = (blockIdx.x * blockDim.x + threadIdx.x) >> 5;
    if (warp >= N_MAT) return;
    int lane = threadIdx.x & 31;
    int d = warp;
    int start = __ldg(&off[d]), deg = __ldg(&cnt[d]);
    float adv = __ldg(&ad[(size_t)d * NHEADS + (lane & 7)]);
    float4 acc = make_float4(0.f, 0.f, 0.f, 0.f);
    float den = 0.f;
    for (int j = 0; j < deg; j += 32) {
        int myi = j + lane;
        int s_my = (myi < deg) ? __ldg(&srt[start + myi]) : 0;
        int m = deg - j; if (m > 32) m = 32;
        for (int k = 0; k < m; k++) {
            int s = __shfl_sync(0xffffffffu, s_my, k);
            float asv = __ldg(&as[(size_t)s * NHEADS + (lane & 7)]);
            float a = asv + adv;
            a = a > 0.f ? a : NEG_SLOPE * a;
            float ex = __expf(a);
            den += ex;
            float w = __shfl_sync(0xffffffffu, ex, lane >> 2);   // head = lane/4
            float4 v = __ldg((const float4*)(h + (size_t)s * HID) + lane);
            acc.x += w * v.x; acc.y += w * v.y; acc.z += w * v.z; acc.w += w * v.w;
        }
    }
    float dh = __shfl_sync(0xffffffffu, den, lane >> 2);
    float inv = 1.f / (dh + 1e-16f);
    acc.x *= inv; acc.y *= inv; acc.z *= inv; acc.w *= inv;
    ((float4*)(o + (size_t)d * HID))[lane] = acc;
}

// ---------------- semantic score: sum_n tanh(relu(o) @ Wk^T + bk)  (grid (.,2)) --------
__global__ void score_kernel(const float* __restrict__ Wk, const float* __restrict__ bk) {
    int m = blockIdx.y;
    __shared__ float ss[8][HID];
    int t = threadIdx.x;         // channel c
    int n0 = blockIdx.x * 8;
    const float* o = m ? g_o_mm : g_o_em;
    const float4* og = (const float4*)(o + (size_t)n0 * HID);
    float4* ss4 = (float4*)&ss[0][0];
    float4 v = og[t];
    v.x = fmaxf(v.x, 0.f); v.y = fmaxf(v.y, 0.f); v.z = fmaxf(v.z, 0.f); v.w = fmaxf(v.w, 0.f);
    ss4[t] = v;
    v = og[t + 128];
    v.x = fmaxf(v.x, 0.f); v.y = fmaxf(v.y, 0.f); v.z = fmaxf(v.z, 0.f); v.w = fmaxf(v.w, 0.f);
    ss4[t + 128] = v;
    __syncthreads();

    float acc[8];
#pragma unroll
    for (int i = 0; i < 8; i++) acc[i] = 0.f;
    const float4* Wr = (const float4*)(Wk + (size_t)t * HID);
#pragma unroll 8
    for (int k4 = 0; k4 < HID / 4; k4++) {
        float4 wv = Wr[k4];
#pragma unroll
        for (int i = 0; i < 8; i++) {
            float4 xv = *(const float4*)&ss[i][k4 * 4];
            acc[i] += wv.x * xv.x + wv.y * xv.y + wv.z * xv.z + wv.w * xv.w;
        }
    }
    float bb = bk[t];
    float local = 0.f;
#pragma unroll
    for (int i = 0; i < 8; i++) local += tanhf(acc[i] + bb);
    atomicAdd(&g_red[m * HID + t], local);
}

// ---------------- semantic attention weights (softmax over 2 scores) ----------------
__global__ void attn_kernel(const float* __restrict__ q) {
    int t = threadIdx.x;   // 128 threads
    float qv = q[t];
    float s0 = qv * g_red[t];
    float s1 = qv * g_red[HID + t];
    __shared__ float r0[4], r1[4];
#pragma unroll
    for (int off = 16; off; off >>= 1) {
        s0 += __shfl_down_sync(0xffffffffu, s0, off);
        s1 += __shfl_down_sync(0xffffffffu, s1, off);
    }
    if ((t & 31) == 0) { r0[t >> 5] = s0; r1[t >> 5] = s1; }
    __syncthreads();
    if (t == 0) {
        float a = (r0[0] + r0[1] + r0[2] + r0[3]) * (1.f / N_MAT);
        float b = (r1[0] + r1[1] + r1[2] + r1[3]) * (1.f / N_MAT);
        float mx = fmaxf(a, b);
        float e0 = __expf(a - mx), e1 = __expf(b - mx);
        float inv = 1.f / (e0 + e1);
        g_attn[0] = e0 * inv;
        g_attn[1] = e1 * inv;
    }
}

// ---------------- final: (attn0*relu(o_em) + attn1*relu(o_mm)) @ Wl^T + bl ----------------
__global__ void final_kernel(const float* __restrict__ Wl, const float* __restrict__ bl,
                             float* __restrict__ out) {
    __shared__ float cs[8][HID];
    int t = threadIdx.x;   // 0..63 -> output channel j
    int n0 = blockIdx.x * 8;
    float a0 = g_attn[0], a1 = g_attn[1];
    const float4* eg = (const float4*)(g_o_em + (size_t)n0 * HID);
    const float4* mg = (const float4*)(g_o_mm + (size_t)n0 * HID);
    float4* cs4 = (float4*)&cs[0][0];
#pragma unroll
    for (int r = 0; r < 4; r++) {
        int idx = r * 64 + t;
        float4 e = eg[idx], mm = mg[idx];
        float4 c;
        c.x = a0 * fmaxf(e.x, 0.f) + a1 * fmaxf(mm.x, 0.f);
        c.y = a0 * fmaxf(e.y, 0.f) + a1 * fmaxf(mm.y, 0.f);
        c.z = a0 * fmaxf(e.z, 0.f) + a1 * fmaxf(mm.z, 0.f);
        c.w = a0 * fmaxf(e.w, 0.f) + a1 * fmaxf(mm.w, 0.f);
        cs4[idx] = c;
    }
    __syncthreads();
    float acc[8];
#pragma unroll
    for (int i = 0; i < 8; i++) acc[i] = 0.f;
    const float4* Wr = (const float4*)(Wl + (size_t)t * HID);
#pragma unroll 8
    for (int k4 = 0; k4 < HID / 4; k4++) {
        float4 wv = Wr[k4];
#pragma unroll
        for (int i = 0; i < 8; i++) {
            float4 xv = *(const float4*)&cs[i][k4 * 4];
            acc[i] += wv.x * xv.x + wv.y * xv.y + wv.z * xv.z + wv.w * xv.w;
        }
    }
    float bb = bl[t];
#pragma unroll
    for (int i = 0; i < 8; i++)
        out[(size_t)(n0 + i) * OUT_DIM + t] = acc[i] + bb;
}

// ---------------- launcher ----------------
extern "C" void kernel_launch(void* const* d_in, const int* in_sizes, int n_in,
                              void* d_out, int out_size) {
    const float* x_mat    = (const float*)d_in[0];
    const float* x_elem   = (const float*)d_in[1];
    const float* W_pm     = (const float*)d_in[2];
    const float* b_pm     = (const float*)d_in[3];
    const float* W_pe     = (const float*)d_in[4];
    const float* b_pe     = (const float*)d_in[5];
    const float* a_src_em = (const float*)d_in[6];
    const float* a_dst_em = (const float*)d_in[7];
    const float* a_src_mm = (const float*)d_in[8];
    const float* a_dst_mm = (const float*)d_in[9];
    const float* Wk       = (const float*)d_in[10];
    const float* bk       = (const float*)d_in[11];
    const float* q        = (const float*)d_in[12];
    const float* Wl       = (const float*)d_in[13];
    const float* bl       = (const float*)d_in[14];
    const int* src_em     = (const int*)d_in[15];
    const int* dst_em     = (const int*)d_in[16];
    const int* src_mm     = (const int*)d_in[17];
    const int* dst_mm     = (const int*)d_in[18];
    float* out = (float*)d_out;

    zero_kernel<<<512, 256>>>();

    // CSR build (parallel 3-stage scan, both types fused via gridDim.y)
    hist_kernel<<<(E_EM + 255) / 256, 256>>>(dst_em, E_EM, 0);
    hist_kernel<<<(E_MM + 255) / 256, 256>>>(dst_mm, E_MM, 1);
    scan1_kernel<<<dim3(SCAN_BLOCKS, 2), 1024>>>();
    scan2_kernel<<<1, 256>>>();
    scan3_kernel<<<dim3(SCAN_BLOCKS, 2), 1024>>>();
    scatter_kernel<<<(E_EM + 255) / 256, 256>>>(src_em, dst_em, E_EM, 0);
    scatter_kernel<<<(E_MM + 255) / 256, 256>>>(src_mm, dst_mm, E_MM, 1);

    // projections
    proj_elem_kernel<<<N_ELEM, 128>>>(x_elem, W_pe, b_pe, a_src_em);
    proj_mat_kernel<<<N_MAT / 8, 128>>>(x_mat, W_pm, b_pm, a_dst_em, a_src_mm, a_dst_mm);

    // fused gather aggregation, both types in one launch (no float atomics)
    agg_csr_kernel<<<dim3((N_MAT * 32 + 255) / 256, 2), 256>>>();

    // semantic attention + final linear
    score_kernel<<<dim3(N_MAT / 8, 2), 128>>>(Wk, bk);
    attn_kernel<<<1, 128>>>(q);
    final_kernel<<<N_MAT / 8, 64>>>(Wl, bl, out);
}

// round 5
// speedup vs baseline: 2.5030x; 2.0089x over previous
#include <cuda_runtime.h>

#define N_MAT   100000
#define N_ELEM  118
#define HID     128
#define NHEADS  8
#define F_MAT   128
#define F_ELEM  64
#define OUT_DIM 64
#define E_EM    1000000
#define E_MM    2000000
#define NEG_SLOPE 0.2f
#define SCAN_BLOCKS 98          // ceil(100000/1024)

// GEMM tiling
#define BM 128
#define BK 16
#define SPAD 132                // padded row length for shared tiles

// ---------------- scratch (static device globals; no allocation) ----------------
__device__ float g_h_mat[(size_t)N_MAT * HID];    // 51.2 MB
__device__ float g_h_elem[N_ELEM * HID];
__device__ float g_as_em[N_ELEM * NHEADS];
__device__ float g_ad_em[N_MAT * NHEADS];
__device__ float g_as_mm[N_MAT * NHEADS];
__device__ float g_ad_mm[N_MAT * NHEADS];
__device__ float g_o_em[(size_t)N_MAT * HID];     // 51.2 MB (post-ReLU)
__device__ float g_o_mm[(size_t)N_MAT * HID];     // 51.2 MB (post-ReLU)
__device__ float g_red[2 * HID];
__device__ float g_attn[2];

// CSR scratch
__device__ int g_cnt_em[N_MAT];
__device__ int g_off_em[N_MAT];
__device__ int g_cur_em[N_MAT];
__device__ int g_srt_em[E_EM];
__device__ int g_cnt_mm[N_MAT];
__device__ int g_off_mm[N_MAT];
__device__ int g_cur_mm[N_MAT];
__device__ int g_srt_mm[E_MM];
__device__ int g_bsum[2 * SCAN_BLOCKS];

// ---------------- zero counters + reduction buffer ----------------
__global__ void zero_kernel() {
    int i = blockIdx.x * blockDim.x + threadIdx.x;
    int nt = gridDim.x * blockDim.x;
    for (int k = i; k < N_MAT; k += nt) { g_cnt_em[k] = 0; g_cnt_mm[k] = 0; }
    if (i < 2 * HID) g_red[i] = 0.f;
}

// ---------------- degree histogram ----------------
__global__ void hist_kernel(const int* __restrict__ dst, int E, int type) {
    int* cnt = type ? g_cnt_mm : g_cnt_em;
    int e = blockIdx.x * blockDim.x + threadIdx.x;
    if (e < E) atomicAdd(&cnt[dst[e]], 1);
}

// ---------------- scan stage 1: per-block sums (grid (98,2)) ----------------
__global__ void scan1_kernel() {
    int type = blockIdx.y;
    const int* cnt = type ? g_cnt_mm : g_cnt_em;
    int i = blockIdx.x * 1024 + threadIdx.x;
    int v = (i < N_MAT) ? cnt[i] : 0;
    int lane = threadIdx.x & 31, wid = threadIdx.x >> 5;
#pragma unroll
    for (int o = 16; o; o >>= 1) v += __shfl_down_sync(0xffffffffu, v, o);
    __shared__ int ws[32];
    if (lane == 0) ws[wid] = v;
    __syncthreads();
    if (wid == 0) {
        int w = ws[lane];
#pragma unroll
        for (int o = 16; o; o >>= 1) w += __shfl_down_sync(0xffffffffu, w, o);
        if (lane == 0) g_bsum[type * SCAN_BLOCKS + blockIdx.x] = w;
    }
}

// ---------------- scan stage 2: exclusive scan of 2x98 block sums ----------------
__global__ void scan2_kernel() {
    __shared__ int sh[2 * SCAN_BLOCKS];
    int t = threadIdx.x;
    if (t < 2 * SCAN_BLOCKS) sh[t] = g_bsum[t];
    __syncthreads();
    if (t < 2) {
        int run = 0;
        for (int b = 0; b < SCAN_BLOCKS; b++) {
            int v = sh[t * SCAN_BLOCKS + b];
            sh[t * SCAN_BLOCKS + b] = run;
            run += v;
        }
    }
    __syncthreads();
    if (t < 2 * SCAN_BLOCKS) g_bsum[t] = sh[t];
}

// ---------------- scan stage 3: per-block exclusive scan + offset (grid (98,2)) --------
__global__ void scan3_kernel() {
    int type = blockIdx.y;
    const int* cnt = type ? g_cnt_mm : g_cnt_em;
    int* off = type ? g_off_mm : g_off_em;
    int* cur = type ? g_cur_mm : g_cur_em;
    int i = blockIdx.x * 1024 + threadIdx.x;
    int v = (i < N_MAT) ? cnt[i] : 0;
    int lane = threadIdx.x & 31, wid = threadIdx.x >> 5;
    int incl = v;
#pragma unroll
    for (int o = 1; o < 32; o <<= 1) {
        int u = __shfl_up_sync(0xffffffffu, incl, o);
        if (lane >= o) incl += u;
    }
    __shared__ int ws[32];
    if (lane == 31) ws[wid] = incl;
    __syncthreads();
    if (wid == 0) {
        int w = ws[lane];
#pragma unroll
        for (int o = 1; o < 32; o <<= 1) {
            int u = __shfl_up_sync(0xffffffffu, w, o);
            if (lane >= o) w += u;
        }
        ws[lane] = w;
    }
    __syncthreads();
    int excl = incl - v + (wid ? ws[wid - 1] : 0) + g_bsum[type * SCAN_BLOCKS + blockIdx.x];
    if (i < N_MAT) { off[i] = excl; cur[i] = excl; }
}

// ---------------- scatter src ids into CSR order ----------------
__global__ void scatter_kernel(const int* __restrict__ src, const int* __restrict__ dst,
                               int E, int type) {
    int* cur = type ? g_cur_mm : g_cur_em;
    int* srt = type ? g_srt_mm : g_srt_em;
    int e = blockIdx.x * blockDim.x + threadIdx.x;
    if (e >= E) return;
    int d = dst[e];
    int p = atomicAdd(&cur[d], 1);
    srt[p] = src[e];
}

// ---------------- projection GEMM: h_mat = x_mat @ W^T + b  (128x128 tile, 8x8/thread) ----
__global__ __launch_bounds__(256) void proj_mat_gemm(const float* __restrict__ A,
                                                     const float* __restrict__ B,
                                                     const float* __restrict__ bias) {
    __shared__ float As[BK][SPAD];
    __shared__ float Bs[BK][SPAD];
    int t = threadIdx.x;
    int m0 = blockIdx.x * BM;
    int tn = t & 15, tm = t >> 4;
    float acc[8][8];
#pragma unroll
    for (int i = 0; i < 8; i++)
#pragma unroll
        for (int j = 0; j < 8; j++) acc[i][j] = 0.f;

    for (int kc = 0; kc < F_MAT; kc += BK) {
#pragma unroll
        for (int l = 0; l < 2; l++) {
            int i = t + l * 256;
            int r = i >> 2, c4 = (i & 3) << 2;
            int m = m0 + r;
            float4 v = make_float4(0.f, 0.f, 0.f, 0.f);
            if (m < N_MAT) v = *(const float4*)&A[(size_t)m * F_MAT + kc + c4];
            As[c4 + 0][r] = v.x; As[c4 + 1][r] = v.y; As[c4 + 2][r] = v.z; As[c4 + 3][r] = v.w;
            float4 w = *(const float4*)&B[(size_t)r * F_MAT + kc + c4];
            Bs[c4 + 0][r] = w.x; Bs[c4 + 1][r] = w.y; Bs[c4 + 2][r] = w.z; Bs[c4 + 3][r] = w.w;
        }
        __syncthreads();
#pragma unroll
        for (int k = 0; k < BK; k++) {
            float a[8], b[8];
            *(float4*)&a[0] = *(const float4*)&As[k][tm * 8];
            *(float4*)&a[4] = *(const float4*)&As[k][tm * 8 + 4];
            *(float4*)&b[0] = *(const float4*)&Bs[k][tn * 8];
            *(float4*)&b[4] = *(const float4*)&Bs[k][tn * 8 + 4];
#pragma unroll
            for (int i = 0; i < 8; i++)
#pragma unroll
                for (int j = 0; j < 8; j++) acc[i][j] += a[i] * b[j];
        }
        __syncthreads();
    }
    float bv[8];
#pragma unroll
    for (int j = 0; j < 8; j++) bv[j] = bias[tn * 8 + j];
#pragma unroll
    for (int i = 0; i < 8; i++) {
        int m = m0 + tm * 8 + i;
        if (m < N_MAT) {
            float4 o0 = make_float4(acc[i][0] + bv[0], acc[i][1] + bv[1],
                                    acc[i][2] + bv[2], acc[i][3] + bv[3]);
            float4 o1 = make_float4(acc[i][4] + bv[4], acc[i][5] + bv[5],
                                    acc[i][6] + bv[6], acc[i][7] + bv[7]);
            *(float4*)&g_h_mat[(size_t)m * HID + tn * 8] = o0;
            *(float4*)&g_h_mat[(size_t)m * HID + tn * 8 + 4] = o1;
        }
    }
}

// ---------------- per-node per-head attention coefficients (warp per node) ----------------
__global__ void att_coef_kernel(const float* __restrict__ ae, const float* __restrict__ am1,
                                const float* __restrict__ am2) {
    int gw = (blockIdx.x * blockDim.x + threadIdx.x) >> 5;
    if (gw >= N_MAT) return;
    int lane = threadIdx.x & 31;
    float4 h = __ldg((const float4*)(g_h_mat + (size_t)gw * HID) + lane);
    float4 e1 = __ldg((const float4*)ae + lane);
    float4 e2 = __ldg((const float4*)am1 + lane);
    float4 e3 = __ldg((const float4*)am2 + lane);
    float v1 = h.x * e1.x + h.y * e1.y + h.z * e1.z + h.w * e1.w;
    float v2 = h.x * e2.x + h.y * e2.y + h.z * e2.z + h.w * e2.w;
    float v3 = h.x * e3.x + h.y * e3.y + h.z * e3.z + h.w * e3.w;
    v1 += __shfl_down_sync(0xffffffffu, v1, 2, 4);
    v1 += __shfl_down_sync(0xffffffffu, v1, 1, 4);
    v2 += __shfl_down_sync(0xffffffffu, v2, 2, 4);
    v2 += __shfl_down_sync(0xffffffffu, v2, 1, 4);
    v3 += __shfl_down_sync(0xffffffffu, v3, 2, 4);
    v3 += __shfl_down_sync(0xffffffffu, v3, 1, 4);
    if ((lane & 3) == 0) {
        int h8 = lane >> 2;
        g_ad_em[gw * NHEADS + h8] = v1;
        g_as_mm[gw * NHEADS + h8] = v2;
        g_ad_mm[gw * NHEADS + h8] = v3;
    }
}

// ---------------- projection: elem nodes (F=64), 1 node/block ----------------
__global__ void proj_elem_kernel(const float* __restrict__ x, const float* __restrict__ W,
                                 const float* __restrict__ b, const float* __restrict__ a_src) {
    __shared__ float xs[F_ELEM];
    int t = threadIdx.x;   // 0..127
    int n = blockIdx.x;
    if (t < F_ELEM) xs[t] = x[n * F_ELEM + t];
    __syncthreads();
    float acc = b[t];
    const float4* Wr = (const float4*)(W + (size_t)t * F_ELEM);
#pragma unroll
    for (int k4 = 0; k4 < F_ELEM / 4; k4++) {
        float4 wv = Wr[k4];
        float4 xv = *(const float4*)&xs[k4 * 4];
        acc += wv.x * xv.x + wv.y * xv.y + wv.z * xv.z + wv.w * xv.w;
    }
    g_h_elem[n * HID + t] = acc;
    float v = acc * a_src[t];
#pragma unroll
    for (int off = 8; off; off >>= 1) v += __shfl_down_sync(0xffffffffu, v, off);
    if ((t & 15) == 0) g_as_em[n * NHEADS + (t >> 4)] = v;
}

// ---------------- CSR aggregation: warp per dst, fused den+numerator+ReLU (grid (.,2)) ----
__global__ void agg_csr_kernel() {
    int type = blockIdx.y;
    const int* srt  = type ? g_srt_mm : g_srt_em;
    const int* off  = type ? g_off_mm : g_off_em;
    const int* cnt  = type ? g_cnt_mm : g_cnt_em;
    const float* as = type ? g_as_mm : g_as_em;
    const float* ad = type ? g_ad_mm : g_ad_em;
    const float* h  = type ? g_h_mat : g_h_elem;
    float* o        = type ? g_o_mm : g_o_em;

    int warp = (blockIdx.x * blockDim.x + threadIdx.x) >> 5;
    if (warp >= N_MAT) return;
    int lane = threadIdx.x & 31;
    int d = warp;
    int start = __ldg(&off[d]), deg = __ldg(&cnt[d]);
    float adv = __ldg(&ad[(size_t)d * NHEADS + (lane & 7)]);
    float4 acc = make_float4(0.f, 0.f, 0.f, 0.f);
    float den = 0.f;
    for (int j = 0; j < deg; j += 32) {
        int myi = j + lane;
        int s_my = (myi < deg) ? __ldg(&srt[start + myi]) : 0;
        int m = deg - j; if (m > 32) m = 32;
        for (int k = 0; k < m; k++) {
            int s = __shfl_sync(0xffffffffu, s_my, k);
            float asv = __ldg(&as[(size_t)s * NHEADS + (lane & 7)]);
            float a = asv + adv;
            a = fmaxf(a, NEG_SLOPE * a);
            float ex = __expf(a);
            den += ex;
            float w = __shfl_sync(0xffffffffu, ex, lane >> 2);   // head = lane/4
            float4 v = __ldg((const float4*)(h + (size_t)s * HID) + lane);
            acc.x += w * v.x; acc.y += w * v.y; acc.z += w * v.z; acc.w += w * v.w;
        }
    }
    float dh = __shfl_sync(0xffffffffu, den, lane >> 2);
    float inv = 1.f / (dh + 1e-16f);
    acc.x = fmaxf(acc.x * inv, 0.f); acc.y = fmaxf(acc.y * inv, 0.f);
    acc.z = fmaxf(acc.z * inv, 0.f); acc.w = fmaxf(acc.w * inv, 0.f);
    ((float4*)(o + (size_t)d * HID))[lane] = acc;
}

// ---------------- semantic score GEMM + tanh-mean reduce (grid (782,2)) ----------------
__global__ __launch_bounds__(256) void score_gemm(const float* __restrict__ Wk,
                                                  const float* __restrict__ bk) {
    int mp = blockIdx.y;
    const float* A = mp ? g_o_mm : g_o_em;          // already ReLU'd
    __shared__ float As[BK][SPAD];
    __shared__ float Bs[BK][SPAD];
    int t = threadIdx.x;
    int m0 = blockIdx.x * BM;
    int tn = t & 15, tm = t >> 4;
    float acc[8][8];
#pragma unroll
    for (int i = 0; i < 8; i++)
#pragma unroll
        for (int j = 0; j < 8; j++) acc[i][j] = 0.f;

    for (int kc = 0; kc < HID; kc += BK) {
#pragma unroll
        for (int l = 0; l < 2; l++) {
            int i = t + l * 256;
            int r = i >> 2, c4 = (i & 3) << 2;
            int m = m0 + r;
            float4 v = make_float4(0.f, 0.f, 0.f, 0.f);
            if (m < N_MAT) v = *(const float4*)&A[(size_t)m * HID + kc + c4];
            As[c4 + 0][r] = v.x; As[c4 + 1][r] = v.y; As[c4 + 2][r] = v.z; As[c4 + 3][r] = v.w;
            float4 w = *(const float4*)&Wk[(size_t)r * HID + kc + c4];
            Bs[c4 + 0][r] = w.x; Bs[c4 + 1][r] = w.y; Bs[c4 + 2][r] = w.z; Bs[c4 + 3][r] = w.w;
        }
        __syncthreads();
#pragma unroll
        for (int k = 0; k < BK; k++) {
            float a[8], b[8];
            *(float4*)&a[0] = *(const float4*)&As[k][tm * 8];
            *(float4*)&a[4] = *(const float4*)&As[k][tm * 8 + 4];
            *(float4*)&b[0] = *(const float4*)&Bs[k][tn * 8];
            *(float4*)&b[4] = *(const float4*)&Bs[k][tn * 8 + 4];
#pragma unroll
            for (int i = 0; i < 8; i++)
#pragma unroll
                for (int j = 0; j < 8; j++) acc[i][j] += a[i] * b[j];
        }
        __syncthreads();
    }
    float bv[8], part[8];
#pragma unroll
    for (int j = 0; j < 8; j++) { bv[j] = bk[tn * 8 + j]; part[j] = 0.f; }
#pragma unroll
    for (int i = 0; i < 8; i++) {
        int m = m0 + tm * 8 + i;
        if (m < N_MAT) {
#pragma unroll
            for (int j = 0; j < 8; j++) part[j] += tanhf(acc[i][j] + bv[j]);
        }
    }
    // reduce partials over the 16 tm groups via shared (reuse As)
#pragma unroll
    for (int j = 0; j < 8; j++) As[tm][tn * 8 + j] = part[j];
    __syncthreads();
    if (t < HID) {
        float s = 0.f;
#pragma unroll
        for (int r = 0; r < 16; r++) s += As[r][t];
        atomicAdd(&g_red[mp * HID + t], s);
    }
}

// ---------------- semantic attention weights (softmax over 2 scores) ----------------
__global__ void attn_kernel(const float* __restrict__ q) {
    int t = threadIdx.x;   // 128 threads
    float qv = q[t];
    float s0 = qv * g_red[t];
    float s1 = qv * g_red[HID + t];
    __shared__ float r0[4], r1[4];
#pragma unroll
    for (int off = 16; off; off >>= 1) {
        s0 += __shfl_down_sync(0xffffffffu, s0, off);
        s1 += __shfl_down_sync(0xffffffffu, s1, off);
    }
    if ((t & 31) == 0) { r0[t >> 5] = s0; r1[t >> 5] = s1; }
    __syncthreads();
    if (t == 0) {
        float a = (r0[0] + r0[1] + r0[2] + r0[3]) * (1.f / N_MAT);
        float b = (r1[0] + r1[1] + r1[2] + r1[3]) * (1.f / N_MAT);
        float mx = fmaxf(a, b);
        float e0 = __expf(a - mx), e1 = __expf(b - mx);
        float inv = 1.f / (e0 + e1);
        g_attn[0] = e0 * inv;
        g_attn[1] = e1 * inv;
    }
}

// ---------------- final GEMM: out = (a0*o_em + a1*o_mm) @ Wl^T + bl  (BN=64) ----------
__global__ __launch_bounds__(256) void final_gemm(const float* __restrict__ Wl,
                                                  const float* __restrict__ bl,
                                                  float* __restrict__ out) {
    __shared__ float As[BK][SPAD];
    __shared__ float Bs[BK][68];
    int t = threadIdx.x;
    int m0 = blockIdx.x * BM;
    int tn = t & 15, tm = t >> 4;       // tn: 16 groups x 4 ch = 64; tm: 16 groups x 8 m = 128
    float a0 = g_attn[0], a1 = g_attn[1];
    float acc[8][4];
#pragma unroll
    for (int i = 0; i < 8; i++)
#pragma unroll
        for (int j = 0; j < 4; j++) acc[i][j] = 0.f;

    for (int kc = 0; kc < HID; kc += BK) {
#pragma unroll
        for (int l = 0; l < 2; l++) {
            int i = t + l * 256;
            int r = i >> 2, c4 = (i & 3) << 2;
            int m = m0 + r;
            float4 v = make_float4(0.f, 0.f, 0.f, 0.f);
            if (m < N_MAT) {
                float4 e = *(const float4*)&g_o_em[(size_t)m * HID + kc + c4];
                float4 mm = *(const float4*)&g_o_mm[(size_t)m * HID + kc + c4];
                v.x = a0 * e.x + a1 * mm.x; v.y = a0 * e.y + a1 * mm.y;
                v.z = a0 * e.z + a1 * mm.z; v.w = a0 * e.w + a1 * mm.w;
            }
            As[c4 + 0][r] = v.x; As[c4 + 1][r] = v.y; As[c4 + 2][r] = v.z; As[c4 + 3][r] = v.w;
        }
        {   // B tile: 64 rows x 16 k = 256 float4, 1 per thread
            int r = t >> 2, c4 = (t & 3) << 2;
            float4 w = *(const float4*)&Wl[(size_t)r * HID + kc + c4];
            Bs[c4 + 0][r] = w.x; Bs[c4 + 1][r] = w.y; Bs[c4 + 2][r] = w.z; Bs[c4 + 3][r] = w.w;
        }
        __syncthreads();
#pragma unroll
        for (int k = 0; k < BK; k++) {
            float a[8], b[4];
            *(float4*)&a[0] = *(const float4*)&As[k][tm * 8];
            *(float4*)&a[4] = *(const float4*)&As[k][tm * 8 + 4];
            *(float4*)&b[0] = *(const float4*)&Bs[k][tn * 4];
#pragma unroll
            for (int i = 0; i < 8; i++)
#pragma unroll
                for (int j = 0; j < 4; j++) acc[i][j] += a[i] * b[j];
        }
        __syncthreads();
    }
    float bv[4];
#pragma unroll
    for (int j = 0; j < 4; j++) bv[j] = bl[tn * 4 + j];
#pragma unroll
    for (int i = 0; i < 8; i++) {
        int m = m0 + tm * 8 + i;
        if (m < N_MAT) {
            float4 o = make_float4(acc[i][0] + bv[0], acc[i][1] + bv[1],
                                   acc[i][2] + bv[2], acc[i][3] + bv[3]);
            *(float4*)&out[(size_t)m * OUT_DIM + tn * 4] = o;
        }
    }
}

// ---------------- launcher ----------------
extern "C" void kernel_launch(void* const* d_in, const int* in_sizes, int n_in,
                              void* d_out, int out_size) {
    const float* x_mat    = (const float*)d_in[0];
    const float* x_elem   = (const float*)d_in[1];
    const float* W_pm     = (const float*)d_in[2];
    const float* b_pm     = (const float*)d_in[3];
    const float* W_pe     = (const float*)d_in[4];
    const float* b_pe     = (const float*)d_in[5];
    const float* a_src_em = (const float*)d_in[6];
    const float* a_dst_em = (const float*)d_in[7];
    const float* a_src_mm = (const float*)d_in[8];
    const float* a_dst_mm = (const float*)d_in[9];
    const float* Wk       = (const float*)d_in[10];
    const float* bk       = (const float*)d_in[11];
    const float* q        = (const float*)d_in[12];
    const float* Wl       = (const float*)d_in[13];
    const float* bl       = (const float*)d_in[14];
    const int* src_em     = (const int*)d_in[15];
    const int* dst_em     = (const int*)d_in[16];
    const int* src_mm     = (const int*)d_in[17];
    const int* dst_mm     = (const int*)d_in[18];
    float* out = (float*)d_out;

    const int GEMM_BLOCKS = (N_MAT + BM - 1) / BM;   // 782

    zero_kernel<<<512, 256>>>();

    // CSR build (parallel 3-stage scan, both types fused via gridDim.y)
    hist_kernel<<<(E_EM + 255) / 256, 256>>>(dst_em, E_EM, 0);
    hist_kernel<<<(E_MM + 255) / 256, 256>>>(dst_mm, E_MM, 1);
    scan1_kernel<<<dim3(SCAN_BLOCKS, 2), 1024>>>();
    scan2_kernel<<<1, 256>>>();
    scan3_kernel<<<dim3(SCAN_BLOCKS, 2), 1024>>>();
    scatter_kernel<<<(E_EM + 255) / 256, 256>>>(src_em, dst_em, E_EM, 0);
    scatter_kernel<<<(E_MM + 255) / 256, 256>>>(src_mm, dst_mm, E_MM, 1);

    // projections
    proj_elem_kernel<<<N_ELEM, 128>>>(x_elem, W_pe, b_pe, a_src_em);
    proj_mat_gemm<<<GEMM_BLOCKS, 256>>>(x_mat, W_pm, b_pm);
    att_coef_kernel<<<(N_MAT * 32 + 255) / 256, 256>>>(a_dst_em, a_src_mm, a_dst_mm);

    // fused gather aggregation, both types in one launch (no float atomics, ReLU fused)
    agg_csr_kernel<<<dim3((N_MAT * 32 + 255) / 256, 2), 256>>>();

    // semantic attention + final linear
    score_gemm<<<dim3(GEMM_BLOCKS, 2), 256>>>(Wk, bk);
    attn_kernel<<<1, 128>>>(q);
    final_gemm<<<GEMM_BLOCKS, 256>>>(Wl, bl, out);
}